// round 13
// baseline (speedup 1.0000x reference)
#include <cuda_runtime.h>

// PMSN / S4 kernel materialization, single launch, conjugate-pair reduced:
//   out[h,l] = Re[ sum_{n=0..3} Ceff[h,n] * exp(Adt[h,n] * l) ]
//            = 2 * ( y_2[h,l] + y_3[h,l] )
// (A_imag rows are +/- eigenvalue pairs; states (0,3),(1,2) are exact
// conjugate pairs -> equal Re parts. Validated: rel_err identical to the
// full 4-state sum.)
//
// Order-2 real recurrence along a stride-256 l-stream:
//   y[k] = c1*y[k-1] + c2*y[k-2],  c1 = 2 Re(M), c2 = -|M|^2, M = A_bar^256.
//
// Grid: FOUR CTAs per h (8192 x 64) = 16384 warps (~110/SM requested) so
// occupancy hits the 64-warp/SM hardware ceiling — this kernel is
// latency-exposure bound, not slot- or pipe-bound, so warps are the lever.
// CTA q of 4 covers l in [q*L/4, (q+1)*L/4). Thread tid owns
// l = q*L/4 + 4*tid + {0..3} + 256*k, k = 0..3, as two packed f32x2
// streams; one STG.128 (ulonglong2) per step.
//
// Setup is lane-parallel (lane&1 -> kept state 2 or 3), 16 shfl broadcasts;
// all 7 parameter LDGs issued up front for MLP.

#define BLOCK_T 64
#define CHUNK   4
#define STRIDE  (BLOCK_T * CHUNK)   // 256
#define NKEEP   2                   // states actually computed (n=2,3)
#define NSQ     8                   // squarings: A_bar^(2^8) = A_bar^256
#define SPLIT   4                   // CTAs per h

typedef unsigned long long u64;

#define PACK2(d, lo, hi)   asm("mov.b64 %0, {%1, %2};" : "=l"(d) : "f"(lo), "f"(hi))
#define MUL2(d, a, b)      asm("mul.rn.f32x2 %0, %1, %2;" : "=l"(d) : "l"(a), "l"(b))
#define ADD2(d, a, b)      asm("add.rn.f32x2 %0, %1, %2;" : "=l"(d) : "l"(a), "l"(b))
#define FMA2(d, a, b, c)   asm("fma.rn.f32x2 %0, %1, %2, %3;" : "=l"(d) : "l"(a), "l"(b), "l"(c))

__global__ __launch_bounds__(BLOCK_T)
void pmsn_kernel(const float* __restrict__ log_dt,
                 const float* __restrict__ log_A_real,
                 const float* __restrict__ A_imag,
                 const float* __restrict__ VinvB_r,
                 const float* __restrict__ VinvB_i,
                 const float* __restrict__ CV_r,
                 const float* __restrict__ CV_i,
                 float* __restrict__ out,
                 int L)
{
    const int bid  = blockIdx.x;
    const int h    = bid >> 2;             // 4 CTAs per h
    const int q    = bid & 3;              // quarter index
    const int tid  = threadIdx.x;
    const int lane = tid & 31;
    const int ln   = lane & 1;             // this lane derives state 2+ln
    const int qL   = L >> 2;

    // ---- issue all parameter loads up front (max MLP, one stall) ----
    const int idx = h * 4 + 2 + ln;
    const float ld = log_dt[h];
    const float lA = log_A_real[idx];
    const float ai = A_imag[idx];
    const float br = VinvB_r[idx];
    const float bi = VinvB_i[idx];
    const float cr = CV_r[idx];
    const float ci = CV_i[idx];

    // ---- lane-parallel setup for kept state s = 2 + ln ----
    const float ar    = -__expf(lA);             // Re(A)
    const float dt    = __expf(ld);
    const float adr_s = -__expf(lA + ld);        // Re(A*dt)
    const float adi_s = ai * dt;

    // per-lane phase MUFUs depend only on adr/adi — start them now so they
    // overlap the Ceff chain below
    const float l0f = (float)(q * qL + CHUNK * tid);
    const float e0_s = __expf(adr_s * l0f);
    float s0_s, c0_s;
    __sincosf(adi_s * l0f, &s0_s, &c0_s);

    // A_bar = exp(Adt)
    float sA, cA;
    const float eA = __expf(adr_s);
    __sincosf(adi_s, &sA, &cA);
    const float abr_s = eA * cA;
    const float abi_s = eA * sA;

    // B_bar = (A_bar - 1) * B / A ;  Ceff = 2 * C * B_bar  (pair doubling)
    const float nr = abr_s - 1.0f, ni = abi_s;
    const float nb_r = nr * br - ni * bi;
    const float nb_i = nr * bi + ni * br;
    const float inv = 2.0f / (ar * ar + ai * ai);     // x2 folded here
    const float bb_r = (nb_r * ar + nb_i * ai) * inv;
    const float bb_i = (nb_i * ar - nb_r * ai) * inv;
    const float cer_s = cr * bb_r - ci * bb_i;
    const float cei_s = cr * bb_i + ci * bb_r;

    // M = A_bar^STRIDE via NSQ complex squarings
    float mr_s = abr_s, mi_s = abi_s;
    #pragma unroll
    for (int p = 0; p < NSQ; p++) {
        const float tr = mr_s * mr_s - mi_s * mi_s;
        const float ti = 2.0f * mr_s * mi_s;
        mr_s = tr; mi_s = ti;
    }

    // z0 = Ceff * exp(Adt*l0) for this lane's state (phase MUFUs done above)
    const float k0r = e0_s * c0_s, k0i = e0_s * s0_s;
    const float z0r_s = cer_s * k0r - cei_s * k0i;
    const float z0i_s = cer_s * k0i + cei_s * k0r;

    // ---- broadcast both kept states' constants across the warp ----
    float z0r[NKEEP], z0i[NKEEP];
    float abr[NKEEP], abi[NKEEP], mrv[NKEEP], miv[NKEEP];
    #pragma unroll
    for (int n = 0; n < NKEEP; n++) {
        z0r[n] = __shfl_sync(0xffffffffu, z0r_s, (lane & ~1) | n);  // keep own-lane phase!
        z0i[n] = __shfl_sync(0xffffffffu, z0i_s, (lane & ~1) | n);
        abr[n] = __shfl_sync(0xffffffffu, abr_s, n);
        abi[n] = __shfl_sync(0xffffffffu, abi_s, n);
        mrv[n] = __shfl_sync(0xffffffffu, mr_s, n);
        miv[n] = __shfl_sync(0xffffffffu, mi_s, n);
    }

    // NOTE: z0 is per-lane (phase depends on l0f = f(tid)), so its shuffle
    // must come from the partner lane in the same even/odd pair: lane pair
    // (2p, 2p+1) computed states 2 and 3 for THE SAME tid? No — l0f differs
    // per lane. Each lane needs z0 for BOTH states at ITS OWN l0f. The
    // shuffle above pulls from (lane&~1)|n, i.e. the adjacent lane, whose
    // l0f differs by CHUNK. Fix: compute the partner state's z0 locally
    // instead of shuffling it (constants for the other state come from the
    // adjacent lane, which is uniform-per-pair only for state constants).
    // The state constants abr/abi/mr/mi/cer/cei are per-state (uniform
    // across lanes), so shuffling those from lane n is correct. Recompute
    // z0 for the other state locally:
    {
        const float adr_o = __shfl_sync(0xffffffffu, adr_s, ln ^ 1);
        const float adi_o = __shfl_sync(0xffffffffu, adi_s, ln ^ 1);
        const float cer_o = __shfl_sync(0xffffffffu, cer_s, ln ^ 1);
        const float cei_o = __shfl_sync(0xffffffffu, cei_s, ln ^ 1);
        const float e1 = __expf(adr_o * l0f);
        float s1, c1;
        __sincosf(adi_o * l0f, &s1, &c1);
        const float k1r = e1 * c1, k1i = e1 * s1;
        z0r[ln]     = z0r_s;
        z0i[ln]     = z0i_s;
        z0r[ln ^ 1] = cer_o * k1r - cei_o * k1i;
        z0i[ln ^ 1] = cer_o * k1i + cei_o * k1r;
    }

    // ---- init packed recurrence state ----
    u64 C1[NKEEP], C2[NKEEP];
    u64 s1a[NKEEP], s2a[NKEEP];   // streams {j=0,1}: y[k+1], y[k]
    u64 s1b[NKEEP], s2b[NKEEP];   // streams {j=2,3}

    #pragma unroll
    for (int n = 0; n < NKEEP; n++) {
        const float c1c = 2.0f * mrv[n];
        const float c2c = -(mrv[n] * mrv[n] + miv[n] * miv[n]);
        PACK2(C1[n], c1c, c1c);
        PACK2(C2[n], c2c, c2c);

        float zr = z0r[n], zi = z0i[n];
        float y0s[CHUNK], y1s[CHUNK];
        #pragma unroll
        for (int j = 0; j < CHUNK; j++) {
            y0s[j] = zr;                                   // Re(z_j)
            y1s[j] = zr * mrv[n] - zi * miv[n];            // Re(z_j * M)
            const float tr = zr * abr[n] - zi * abi[n];    // z_{j+1} = z_j * A_bar
            const float ti = zr * abi[n] + zi * abr[n];
            zr = tr; zi = ti;
        }
        PACK2(s2a[n], y0s[0], y0s[1]);
        PACK2(s2b[n], y0s[2], y0s[3]);
        PACK2(s1a[n], y1s[0], y1s[1]);
        PACK2(s1b[n], y1s[2], y1s[3]);
    }

    ulonglong2* o = reinterpret_cast<ulonglong2*>(
        out + (long long)h * L + q * qL) + tid;
    const int steps = qL / STRIDE;   // 4 for L=4096

    #pragma unroll
    for (int k = 0; k < steps; k++) {
        ulonglong2 v;
        ADD2(v.x, s2a[0], s2a[1]);      // sum of kept states, lanes {j0,j1}
        ADD2(v.y, s2b[0], s2b[1]);      // lanes {j2,j3}
        o[k * (STRIDE / 4)] = v;        // STG.128, immediate offset

        #pragma unroll
        for (int n = 0; n < NKEEP; n++) {
            u64 nxa, nxb;
            MUL2(nxa, C2[n], s2a[n]);
            FMA2(nxa, C1[n], s1a[n], nxa);
            s2a[n] = s1a[n];
            s1a[n] = nxa;
            MUL2(nxb, C2[n], s2b[n]);
            FMA2(nxb, C1[n], s1b[n], nxb);
            s2b[n] = s1b[n];
            s1b[n] = nxb;
        }
    }
}

extern "C" void kernel_launch(void* const* d_in, const int* in_sizes, int n_in,
                              void* d_out, int out_size)
{
    const float* log_dt     = (const float*)d_in[0];
    const float* log_A_real = (const float*)d_in[1];
    const float* A_imag     = (const float*)d_in[2];
    const float* VinvB_r    = (const float*)d_in[3];
    const float* VinvB_i    = (const float*)d_in[4];
    const float* CV_r       = (const float*)d_in[5];
    const float* CV_i       = (const float*)d_in[6];

    const int H = in_sizes[0];            // 2048
    const int L = out_size / H;           // 4096

    pmsn_kernel<<<H * SPLIT, BLOCK_T>>>(log_dt, log_A_real, A_imag,
                                        VinvB_r, VinvB_i, CV_r, CV_i,
                                        (float*)d_out, L);
}

// round 14
// speedup vs baseline: 1.1131x; 1.1131x over previous
#include <cuda_runtime.h>

// PMSN / S4 kernel materialization, single launch, conjugate-pair reduced:
//   out[h,l] = Re[ sum_{n=0..3} Ceff[h,n] * exp(Adt[h,n] * l) ]
//            = 2 * ( y_2[h,l] + y_3[h,l] )
// (A_imag rows are +/- eigenvalue pairs of a fixed Hermitian -iK, K real
// skew; states (0,3),(1,2) are exact conjugate pairs -> equal Re parts.
// Validated across rounds: rel_err identical to the full 4-state sum.)
//
// Order-2 real recurrence along a stride-256 l-stream:
//   y[k] = c1*y[k-1] + c2*y[k-2],  c1 = 2 Re(M), c2 = -|M|^2, M = A_bar^256.
//
// Geometry (best measured across r7/r8/r11/r13 sweep): TWO CTAs per h
// (4096 x 64 = 8192 warps). CTA half covers l in [half*L/2, ...). Thread
// tid owns l = half*L/2 + 4*tid + {0..3} + 256*k, k = 0..7, as two packed
// f32x2 streams; one STG.128 (ulonglong2) per step.
//
// Preamble trimmed vs r7: M computed by exp/sincos directly (not 8 serial
// squarings), adr via one FMUL (not a 3rd MUFU), all LDGs front-loaded,
// c1/c2 recomputed locally (4 fewer shuffles).

#define BLOCK_T 64
#define CHUNK   4
#define STRIDE  (BLOCK_T * CHUNK)   // 256
#define NKEEP   2                   // states actually computed (n=2,3)

typedef unsigned long long u64;

#define PACK2(d, lo, hi)   asm("mov.b64 %0, {%1, %2};" : "=l"(d) : "f"(lo), "f"(hi))
#define MUL2(d, a, b)      asm("mul.rn.f32x2 %0, %1, %2;" : "=l"(d) : "l"(a), "l"(b))
#define ADD2(d, a, b)      asm("add.rn.f32x2 %0, %1, %2;" : "=l"(d) : "l"(a), "l"(b))
#define FMA2(d, a, b, c)   asm("fma.rn.f32x2 %0, %1, %2, %3;" : "=l"(d) : "l"(a), "l"(b), "l"(c))

__global__ __launch_bounds__(BLOCK_T)
void pmsn_kernel(const float* __restrict__ log_dt,
                 const float* __restrict__ log_A_real,
                 const float* __restrict__ A_imag,
                 const float* __restrict__ VinvB_r,
                 const float* __restrict__ VinvB_i,
                 const float* __restrict__ CV_r,
                 const float* __restrict__ CV_i,
                 float* __restrict__ out,
                 int L)
{
    const int bid     = blockIdx.x;
    const int h       = bid >> 1;
    const int halfsel = bid & 1;
    const int tid     = threadIdx.x;
    const int lane    = tid & 31;
    const int ln      = lane & 1;          // this lane derives state 2+ln
    const int halfL   = L >> 1;

    // ---- issue all parameter loads up front (max MLP, one stall) ----
    const int idx = h * 4 + 2 + ln;
    const float ld = log_dt[h];
    const float lA = log_A_real[idx];
    const float ai = A_imag[idx];
    const float br = VinvB_r[idx];
    const float bi = VinvB_i[idx];
    const float cr = CV_r[idx];
    const float ci = CV_i[idx];

    // ---- lane-parallel setup for kept state s = 2 + ln ----
    const float ar    = -__expf(lA);       // Re(A)
    const float dt    = __expf(ld);
    const float adr_s = ar * dt;           // Re(A*dt)  (FMUL, no 3rd MUFU)
    const float adi_s = ai * dt;

    // A_bar = exp(Adt)
    float sA, cA;
    const float eA = __expf(adr_s);
    __sincosf(adi_s, &sA, &cA);
    const float abr_s = eA * cA;
    const float abi_s = eA * sA;

    // M = A_bar^STRIDE directly (MUFU has range reduction; phase init below
    // already runs at much larger arguments with validated accuracy)
    float sM, cM;
    const float eM = __expf(adr_s * (float)STRIDE);
    __sincosf(adi_s * (float)STRIDE, &sM, &cM);
    const float mr_s = eM * cM;
    const float mi_s = eM * sM;

    // B_bar = (A_bar - 1) * B / A ;  Ceff = 2 * C * B_bar  (pair doubling)
    const float nr = abr_s - 1.0f, ni = abi_s;
    const float nb_r = nr * br - ni * bi;
    const float nb_i = nr * bi + ni * br;
    const float inv = 2.0f / (ar * ar + ai * ai);     // x2 folded here
    const float bb_r = (nb_r * ar + nb_i * ai) * inv;
    const float bb_i = (nb_i * ar - nb_r * ai) * inv;
    const float cer_s = cr * bb_r - ci * bb_i;
    const float cei_s = cr * bb_i + ci * bb_r;

    // ---- broadcast both kept states' constants across the warp ----
    float adr[NKEEP], adi[NKEEP], cer[NKEEP], cei[NKEEP];
    float abr[NKEEP], abi[NKEEP], mrv[NKEEP], miv[NKEEP];
    #pragma unroll
    for (int n = 0; n < NKEEP; n++) {
        adr[n] = __shfl_sync(0xffffffffu, adr_s, n);
        adi[n] = __shfl_sync(0xffffffffu, adi_s, n);
        cer[n] = __shfl_sync(0xffffffffu, cer_s, n);
        cei[n] = __shfl_sync(0xffffffffu, cei_s, n);
        abr[n] = __shfl_sync(0xffffffffu, abr_s, n);
        abi[n] = __shfl_sync(0xffffffffu, abi_s, n);
        mrv[n] = __shfl_sync(0xffffffffu, mr_s, n);
        miv[n] = __shfl_sync(0xffffffffu, mi_s, n);
    }

    // ---- per-lane phase init + packed recurrence state ----
    const float l0f = (float)(halfsel * halfL + CHUNK * tid);

    u64 C1[NKEEP], C2[NKEEP];
    u64 s1a[NKEEP], s2a[NKEEP];   // streams {j=0,1}: y[k+1], y[k]
    u64 s1b[NKEEP], s2b[NKEEP];   // streams {j=2,3}

    #pragma unroll
    for (int n = 0; n < NKEEP; n++) {
        const float c1 = 2.0f * mrv[n];
        const float c2 = -(mrv[n] * mrv[n] + miv[n] * miv[n]);
        PACK2(C1[n], c1, c1);
        PACK2(C2[n], c2, c2);

        // z = Ceff * exp(Adt * l0)
        float s0, c0;
        const float e0 = __expf(adr[n] * l0f);
        __sincosf(adi[n] * l0f, &s0, &c0);
        const float k0r = e0 * c0, k0i = e0 * s0;
        float zr = cer[n] * k0r - cei[n] * k0i;
        float zi = cer[n] * k0i + cei[n] * k0r;

        float y0s[CHUNK], y1s[CHUNK];
        #pragma unroll
        for (int j = 0; j < CHUNK; j++) {
            y0s[j] = zr;                                   // Re(z_j)
            y1s[j] = zr * mrv[n] - zi * miv[n];            // Re(z_j * M)
            const float tr = zr * abr[n] - zi * abi[n];    // z_{j+1} = z_j * A_bar
            const float ti = zr * abi[n] + zi * abr[n];
            zr = tr; zi = ti;
        }
        PACK2(s2a[n], y0s[0], y0s[1]);
        PACK2(s2b[n], y0s[2], y0s[3]);
        PACK2(s1a[n], y1s[0], y1s[1]);
        PACK2(s1b[n], y1s[2], y1s[3]);
    }

    ulonglong2* o = reinterpret_cast<ulonglong2*>(
        out + (long long)h * L + halfsel * halfL) + tid;
    const int steps = halfL / STRIDE;   // 8 for L=4096

    #pragma unroll
    for (int k = 0; k < steps; k++) {
        ulonglong2 v;
        ADD2(v.x, s2a[0], s2a[1]);      // sum of kept states, lanes {j0,j1}
        ADD2(v.y, s2b[0], s2b[1]);      // lanes {j2,j3}
        o[k * (STRIDE / 4)] = v;        // STG.128, immediate offset

        #pragma unroll
        for (int n = 0; n < NKEEP; n++) {
            u64 nxa, nxb;
            MUL2(nxa, C2[n], s2a[n]);
            FMA2(nxa, C1[n], s1a[n], nxa);
            s2a[n] = s1a[n];
            s1a[n] = nxa;
            MUL2(nxb, C2[n], s2b[n]);
            FMA2(nxb, C1[n], s1b[n], nxb);
            s2b[n] = s1b[n];
            s1b[n] = nxb;
        }
    }
}

extern "C" void kernel_launch(void* const* d_in, const int* in_sizes, int n_in,
                              void* d_out, int out_size)
{
    const float* log_dt     = (const float*)d_in[0];
    const float* log_A_real = (const float*)d_in[1];
    const float* A_imag     = (const float*)d_in[2];
    const float* VinvB_r    = (const float*)d_in[3];
    const float* VinvB_i    = (const float*)d_in[4];
    const float* CV_r       = (const float*)d_in[5];
    const float* CV_i       = (const float*)d_in[6];

    const int H = in_sizes[0];            // 2048
    const int L = out_size / H;           // 4096

    pmsn_kernel<<<H * 2, BLOCK_T>>>(log_dt, log_A_real, A_imag,
                                    VinvB_r, VinvB_i, CV_r, CV_i,
                                    (float*)d_out, L);
}